// round 9
// baseline (speedup 1.0000x reference)
#include <cuda_runtime.h>
#include <math.h>

#define N_IN 12288
#define H0 256
#define H1 32
#define H2 32
#define NB 8192
#define SEG_CAP 32        // per-warp-slice capacity (Binomial(1536,.0025): mean 3.8, z>14 safe)
#define FULL 0xffffffffu

// Transposed ft weights: column j = 256 contiguous floats (12.6 MB, L2-resident).
__device__ float g_ftT[N_IN * H0];
// MLP-ready inputs: [row][512], already side-swapped, +ftb, clamped (16 MB).
__device__ float g_x[NB * 2 * H0];
// 0 = 32-bit words (int32/fp32; !=0 covers both), 1 = packed bytes.
__device__ int g_side_mode;

__global__ void transpose_ft(const float* __restrict__ ftw,
                             const unsigned int* __restrict__ side_words) {
    // Folded side-mode detection: block (0,0), warp 0 (saves a serial launch).
    if (blockIdx.x == 0 && blockIdx.y == 0 && threadIdx.y == 0) {
        int lane = threadIdx.x;
        bool bad = false;
#pragma unroll
        for (int i = 0; i < 8; i++) {
            unsigned int v = side_words[i * 32 + lane];   // 1 KB sample
            bad |= (v != 0u && v != 1u && v != 0x3f800000u);
        }
        unsigned m = __ballot_sync(FULL, bad);
        if (lane == 0) g_side_mode = (m != 0u) ? 1 : 0;
    }
    __shared__ float tile[32][33];
    int j0 = blockIdx.x * 32, h0 = blockIdx.y * 32;
    int tx = threadIdx.x, ty = threadIdx.y;
#pragma unroll
    for (int r = 0; r < 32; r += 8)
        tile[ty + r][tx] = ftw[(size_t)(h0 + ty + r) * N_IN + j0 + tx];
    __syncthreads();
#pragma unroll
    for (int r = 0; r < 32; r += 8)
        g_ftT[(size_t)(j0 + ty + r) * H0 + h0 + tx] = tile[tx][ty + r];
}

__device__ __forceinline__ float clamp01(float x) { return fminf(fmaxf(x, 0.f), 1.f); }
__device__ __forceinline__ void add4(float4& a, float4 u) {
    a.x += u.x; a.y += u.y; a.z += u.z; a.w += u.w;
}

// ============================================================================
// FT (fused scan+gather): one CTA per row-side. DRAM streaming (__ldcs,
// evict-first: protects the L2-resident ft table) overlaps with other CTAs'
// L2 gathers. Epilogue now resolves side-swap, adds ftb, clamps -> g_x is
// MLP-ready (removes the dependent-chain staging that stalled mlp_kernel).
// ============================================================================
__global__ __launch_bounds__(256) void ft_kernel(
    const float* __restrict__ wf, const float* __restrict__ bf,
    const void* __restrict__ side, const float* __restrict__ ftb)
{
    __shared__ unsigned short lists[8][SEG_CAP];
    __shared__ int cnts[8];
    __shared__ float partial[8][H0];

    const int R = blockIdx.x;                       // row-side: row=R>>1, color=R&1
    const int row = R >> 1, color = R & 1;
    const float* base = color ? bf : wf;
    const uint4* rowp = (const uint4*)(base + (size_t)row * N_IN);
    const int t = threadIdx.x, lane = t & 31, wid = t >> 5;
    const unsigned lt = (1u << lane) - 1u;

    // ---- front-batched stream (12x LDG.128/thread), evict-first in L2 ----
    uint4 st[12];
#pragma unroll
    for (int i = 0; i < 12; i++) st[i] = __ldcs(rowp + i * 256 + t);

    // ---- ballot/popc compaction into per-warp smem segment ----
    int n = 0;
    unsigned short* seg = lists[wid];
#pragma unroll
    for (int i = 0; i < 12; i++) {
        uint4 v = st[i];
        bool f0 = v.x != 0u, f1 = v.y != 0u, f2 = v.z != 0u, f3 = v.w != 0u;
        unsigned b0 = __ballot_sync(FULL, f0);
        unsigned b1 = __ballot_sync(FULL, f1);
        unsigned b2 = __ballot_sync(FULL, f2);
        unsigned b3 = __ballot_sync(FULL, f3);
        if (b0 | b1 | b2 | b3) {                     // ~96% all-zero warp-wide
            int ib = (i * 256 + t) * 4;
            int c0 = __popc(b0), c01 = c0 + __popc(b1), c012 = c01 + __popc(b2);
            if (f0) { int q = n + __popc(b0 & lt);        if (q < SEG_CAP) seg[q] = (unsigned short)ib; }
            if (f1) { int q = n + c0 + __popc(b1 & lt);   if (q < SEG_CAP) seg[q] = (unsigned short)(ib + 1); }
            if (f2) { int q = n + c01 + __popc(b2 & lt);  if (q < SEG_CAP) seg[q] = (unsigned short)(ib + 2); }
            if (f3) { int q = n + c012 + __popc(b3 & lt); if (q < SEG_CAP) seg[q] = (unsigned short)(ib + 3); }
            n += c012 + __popc(b3);
        }
    }
    if (lane == 0) cnts[wid] = min(n, SEG_CAP);
    __syncthreads();

    // ---- gather: warp w takes global positions p ≡ w (mod 8) ----
    float4 a0 = make_float4(0, 0, 0, 0), a1 = a0;
    const float4* tab = (const float4*)g_ftT;
    {
        int gpos = 0;
#pragma unroll
        for (int s = 0; s < 8; s++) {
            int c = cnts[s];
            int p0 = gpos + ((wid - gpos) & 7);      // first p ≥ gpos with p%8==wid
            const unsigned short* sl = lists[s];
            for (int p = p0; p < gpos + c; p += 8) {
                int idx = sl[p - gpos];              // warp-uniform broadcast
                const float4* cp = tab + idx * 64 + lane * 2;
                float4 u0 = cp[0], u1 = cp[1];
                add4(a0, u0); add4(a1, u1);
            }
            gpos += c;
        }
    }
    ((float4*)partial[wid])[lane * 2]     = a0;
    ((float4*)partial[wid])[lane * 2 + 1] = a1;
    __syncthreads();

    // ---- fixed-order 8-way reduce + ftb + clamp + side-swap resolve ----
    float sum = partial[0][t];
#pragma unroll
    for (int w = 1; w < 8; w++) sum += partial[w][t];
    sum = clamp01(sum + ftb[t]);

    bool sd = g_side_mode ? (((const unsigned char*)side)[row] != 0)
                          : (((const unsigned int*)side)[row] != 0u);
    // reference: acc = side ? [w,b] : [b,w]; color 0 = white
    int half = (color == 0) ? (sd ? 0 : 1) : (sd ? 1 : 0);
    g_x[(size_t)row * 2 * H0 + half * H0 + t] = sum;
}

// ============================================================================
// MLP: 32 rows/CTA, 4 rows/warp (weight LDS amortized 4x; staging amortized).
// x staging is a pure contiguous float4 copy (g_x is MLP-ready). Lane o owns
// output o -> no shfl chains in l1/l2.
// ============================================================================
struct SmemM {
    float4 w4[32 * 129];     // l1w, stride 129 -> conflict-free LDS.128
    float4 x4[32 * 128];     // 32 rows x 512 inputs
    float o1[32 * 33];
    float l2w[32 * 33];
    float l3w[32], l1b[32], l2b[32];
    float l3b;
};

__global__ __launch_bounds__(256) void mlp_kernel(
    const float* __restrict__ l1w, const float* __restrict__ l1b,
    const float* __restrict__ l2w, const float* __restrict__ l2b,
    const float* __restrict__ l3w, const float* __restrict__ l3b,
    float* __restrict__ out)
{
    extern __shared__ unsigned char raw[];
    SmemM* S = (SmemM*)raw;
    const int t = threadIdx.x, lane = t & 31, wid = t >> 5;
    const int row0 = blockIdx.x * 32;

    for (int i = t; i < 32 * 128; i += 256) {
        int o = i >> 7, k4 = i & 127;
        S->w4[o * 129 + k4] = ((const float4*)l1w)[i];
    }
    {   // pure contiguous copy: 32 rows x 512 floats = 4096 float4
        const float4* src = ((const float4*)g_x) + (size_t)row0 * 128;
        for (int i = t; i < 32 * 128; i += 256) S->x4[i] = src[i];
    }
    for (int i = t; i < 32 * 32; i += 256)
        S->l2w[(i >> 5) * 33 + (i & 31)] = l2w[i];
    if (t < 32) { S->l3w[t] = l3w[t]; S->l1b[t] = l1b[t]; S->l2b[t] = l2b[t]; }
    if (t == 0) S->l3b = l3b[0];
    __syncthreads();

    const int r0 = wid * 4;
    const float4* wr = S->w4 + lane * 129;
    const float4* xa = S->x4 + (r0 + 0) * 128;
    const float4* xb = S->x4 + (r0 + 1) * 128;
    const float4* xc = S->x4 + (r0 + 2) * 128;
    const float4* xd = S->x4 + (r0 + 3) * 128;
    float s0 = 0.f, s1 = 0.f, s2 = 0.f, s3 = 0.f;
#pragma unroll 4
    for (int k = 0; k < 128; k++) {
        float4 wv = wr[k];                            // 1 weight LDS.128 serves 4 rows
        float4 u = xa[k], v = xb[k], p = xc[k], q = xd[k];   // broadcast reads
        s0 += ((wv.x * u.x + wv.y * u.y) + (wv.z * u.z + wv.w * u.w));
        s1 += ((wv.x * v.x + wv.y * v.y) + (wv.z * v.z + wv.w * v.w));
        s2 += ((wv.x * p.x + wv.y * p.y) + (wv.z * p.z + wv.w * p.w));
        s3 += ((wv.x * q.x + wv.y * q.y) + (wv.z * q.z + wv.w * q.w));
    }
    S->o1[(r0 + 0) * 33 + lane] = clamp01(s0 + S->l1b[lane]);
    S->o1[(r0 + 1) * 33 + lane] = clamp01(s1 + S->l1b[lane]);
    S->o1[(r0 + 2) * 33 + lane] = clamp01(s2 + S->l1b[lane]);
    S->o1[(r0 + 3) * 33 + lane] = clamp01(s3 + S->l1b[lane]);
    __syncwarp();

    float t0 = 0.f, t1 = 0.f, t2 = 0.f, t3 = 0.f;
#pragma unroll
    for (int k = 0; k < 32; k++) {
        float w2 = S->l2w[lane * 33 + k];             // (lane+k)%32: conflict-free
        t0 += w2 * S->o1[(r0 + 0) * 33 + k];
        t1 += w2 * S->o1[(r0 + 1) * 33 + k];
        t2 += w2 * S->o1[(r0 + 2) * 33 + k];
        t3 += w2 * S->o1[(r0 + 3) * 33 + k];
    }
    float v0 = clamp01(t0 + S->l2b[lane]) * S->l3w[lane];
    float v1 = clamp01(t1 + S->l2b[lane]) * S->l3w[lane];
    float v2 = clamp01(t2 + S->l2b[lane]) * S->l3w[lane];
    float v3 = clamp01(t3 + S->l2b[lane]) * S->l3w[lane];
#pragma unroll
    for (int off = 16; off; off >>= 1) {
        v0 += __shfl_xor_sync(FULL, v0, off);
        v1 += __shfl_xor_sync(FULL, v1, off);
        v2 += __shfl_xor_sync(FULL, v2, off);
        v3 += __shfl_xor_sync(FULL, v3, off);
    }
    if (lane == 0) {
        float b = S->l3b;
        out[row0 + r0 + 0] = 1.f / (1.f + expf(-(v0 + b) * 1.5f));  // 300/200
        out[row0 + r0 + 1] = 1.f / (1.f + expf(-(v1 + b) * 1.5f));
        out[row0 + r0 + 2] = 1.f / (1.f + expf(-(v2 + b) * 1.5f));
        out[row0 + r0 + 3] = 1.f / (1.f + expf(-(v3 + b) * 1.5f));
    }
}

extern "C" void kernel_launch(void* const* d_in, const int* in_sizes, int n_in,
                              void* d_out, int out_size) {
    const float* wf  = (const float*)d_in[0];
    const float* bf  = (const float*)d_in[1];
    const void*  side = d_in[2];
    const float* ftw = (const float*)d_in[3];
    const float* ftb = (const float*)d_in[4];
    const float* l1w = (const float*)d_in[5];
    const float* l1b = (const float*)d_in[6];
    const float* l2w = (const float*)d_in[7];
    const float* l2b = (const float*)d_in[8];
    const float* l3w = (const float*)d_in[9];
    const float* l3b = (const float*)d_in[10];
    float* out = (float*)d_out;

    cudaFuncSetAttribute(mlp_kernel, cudaFuncAttributeMaxDynamicSharedMemorySize,
                         (int)sizeof(SmemM));

    transpose_ft<<<dim3(N_IN / 32, H0 / 32), dim3(32, 8)>>>(
        ftw, (const unsigned int*)side);
    ft_kernel<<<NB * 2, 256>>>(wf, bf, side, ftb);
    mlp_kernel<<<NB / 32, 256, sizeof(SmemM)>>>(l1w, l1b, l2w, l2b, l3w, l3b, out);
}

// round 10
// speedup vs baseline: 1.0127x; 1.0127x over previous
#include <cuda_runtime.h>
#include <math.h>

#define N_IN 12288
#define H0 256
#define H1 32
#define H2 32
#define NB 8192
#define SEG_CAP 32        // per-warp-slice capacity (Binomial(1536,.0025): mean 3.8, z>14 safe)
#define FULL 0xffffffffu

// Transposed ft weights: column j = 256 contiguous floats (12.6 MB, L2-resident).
__device__ float g_ftT[N_IN * H0];
// MLP-ready inputs: [row][512], already side-swapped, +ftb, clamped (16 MB).
__device__ float g_x[NB * 2 * H0];
// 0 = 32-bit words (int32/fp32; !=0 covers both), 1 = packed bytes.
__device__ int g_side_mode;

__global__ void transpose_ft(const float* __restrict__ ftw,
                             const unsigned int* __restrict__ side_words) {
    // Folded side-mode detection: block (0,0), warp 0 (saves a serial launch).
    if (blockIdx.x == 0 && blockIdx.y == 0 && threadIdx.y == 0) {
        int lane = threadIdx.x;
        bool bad = false;
#pragma unroll
        for (int i = 0; i < 8; i++) {
            unsigned int v = side_words[i * 32 + lane];   // 1 KB sample
            bad |= (v != 0u && v != 1u && v != 0x3f800000u);
        }
        unsigned m = __ballot_sync(FULL, bad);
        if (lane == 0) g_side_mode = (m != 0u) ? 1 : 0;
    }
    __shared__ float tile[32][33];
    int j0 = blockIdx.x * 32, h0 = blockIdx.y * 32;
    int tx = threadIdx.x, ty = threadIdx.y;
#pragma unroll
    for (int r = 0; r < 32; r += 8)
        tile[ty + r][tx] = ftw[(size_t)(h0 + ty + r) * N_IN + j0 + tx];
    __syncthreads();
#pragma unroll
    for (int r = 0; r < 32; r += 8)
        g_ftT[(size_t)(j0 + ty + r) * H0 + h0 + tx] = tile[tx][ty + r];
}

__device__ __forceinline__ float clamp01(float x) { return fminf(fmaxf(x, 0.f), 1.f); }
__device__ __forceinline__ void add4(float4& a, float4 u) {
    a.x += u.x; a.y += u.y; a.z += u.z; a.w += u.w;
}

// ============================================================================
// FT (fused scan+gather): one CTA per row-side. DRAM streaming (__ldcs,
// evict-first: protects the L2-resident ft table) overlaps with other CTAs'
// L2 gathers. Epilogue resolves side-swap, adds ftb, clamps -> g_x is
// MLP-ready. (Unchanged: profiled at the DRAM roofline.)
// ============================================================================
__global__ __launch_bounds__(256) void ft_kernel(
    const float* __restrict__ wf, const float* __restrict__ bf,
    const void* __restrict__ side, const float* __restrict__ ftb)
{
    __shared__ unsigned short lists[8][SEG_CAP];
    __shared__ int cnts[8];
    __shared__ float partial[8][H0];

    const int R = blockIdx.x;                       // row-side: row=R>>1, color=R&1
    const int row = R >> 1, color = R & 1;
    const float* base = color ? bf : wf;
    const uint4* rowp = (const uint4*)(base + (size_t)row * N_IN);
    const int t = threadIdx.x, lane = t & 31, wid = t >> 5;
    const unsigned lt = (1u << lane) - 1u;

    // ---- front-batched stream (12x LDG.128/thread), evict-first in L2 ----
    uint4 st[12];
#pragma unroll
    for (int i = 0; i < 12; i++) st[i] = __ldcs(rowp + i * 256 + t);

    // ---- ballot/popc compaction into per-warp smem segment ----
    int n = 0;
    unsigned short* seg = lists[wid];
#pragma unroll
    for (int i = 0; i < 12; i++) {
        uint4 v = st[i];
        bool f0 = v.x != 0u, f1 = v.y != 0u, f2 = v.z != 0u, f3 = v.w != 0u;
        unsigned b0 = __ballot_sync(FULL, f0);
        unsigned b1 = __ballot_sync(FULL, f1);
        unsigned b2 = __ballot_sync(FULL, f2);
        unsigned b3 = __ballot_sync(FULL, f3);
        if (b0 | b1 | b2 | b3) {                     // ~96% all-zero warp-wide
            int ib = (i * 256 + t) * 4;
            int c0 = __popc(b0), c01 = c0 + __popc(b1), c012 = c01 + __popc(b2);
            if (f0) { int q = n + __popc(b0 & lt);        if (q < SEG_CAP) seg[q] = (unsigned short)ib; }
            if (f1) { int q = n + c0 + __popc(b1 & lt);   if (q < SEG_CAP) seg[q] = (unsigned short)(ib + 1); }
            if (f2) { int q = n + c01 + __popc(b2 & lt);  if (q < SEG_CAP) seg[q] = (unsigned short)(ib + 2); }
            if (f3) { int q = n + c012 + __popc(b3 & lt); if (q < SEG_CAP) seg[q] = (unsigned short)(ib + 3); }
            n += c012 + __popc(b3);
        }
    }
    if (lane == 0) cnts[wid] = min(n, SEG_CAP);
    __syncthreads();

    // ---- gather: warp w takes global positions p ≡ w (mod 8) ----
    float4 a0 = make_float4(0, 0, 0, 0), a1 = a0;
    const float4* tab = (const float4*)g_ftT;
    {
        int gpos = 0;
#pragma unroll
        for (int s = 0; s < 8; s++) {
            int c = cnts[s];
            int p0 = gpos + ((wid - gpos) & 7);      // first p ≥ gpos with p%8==wid
            const unsigned short* sl = lists[s];
            for (int p = p0; p < gpos + c; p += 8) {
                int idx = sl[p - gpos];              // warp-uniform broadcast
                const float4* cp = tab + idx * 64 + lane * 2;
                float4 u0 = cp[0], u1 = cp[1];
                add4(a0, u0); add4(a1, u1);
            }
            gpos += c;
        }
    }
    ((float4*)partial[wid])[lane * 2]     = a0;
    ((float4*)partial[wid])[lane * 2 + 1] = a1;
    __syncthreads();

    // ---- fixed-order 8-way reduce + ftb + clamp + side-swap resolve ----
    float sum = partial[0][t];
#pragma unroll
    for (int w = 1; w < 8; w++) sum += partial[w][t];
    sum = clamp01(sum + ftb[t]);

    bool sd = g_side_mode ? (((const unsigned char*)side)[row] != 0)
                          : (((const unsigned int*)side)[row] != 0u);
    // reference: acc = side ? [w,b] : [b,w]; color 0 = white
    int half = (color == 0) ? (sd ? 0 : 1) : (sd ? 1 : 0);
    g_x[(size_t)row * 2 * H0 + half * H0 + t] = sum;
}

// ============================================================================
// MLP v3: 32 rows/CTA, 4 rows/warp. x is NOT staged in smem — xa[k] reads are
// warp-uniform, so they come straight from L2 as independent uniform LDG.128
// (front-batched by the unroller). Smem = weights only (~75 KB) -> 3 CTAs/SM,
// 24 warps/SM for latency hiding. Lane o owns output o -> no shfl chains.
// ============================================================================
struct SmemM {
    float4 w4[32 * 129];     // l1w, stride 129 -> conflict-free LDS.128
    float o1[32 * 33];
    float l2w[32 * 33];      // (lane+k)%32 conflict-free
    float l3w[32], l1b[32], l2b[32];
    float l3b;
};

__global__ __launch_bounds__(256) void mlp_kernel(
    const float* __restrict__ l1w, const float* __restrict__ l1b,
    const float* __restrict__ l2w, const float* __restrict__ l2b,
    const float* __restrict__ l3w, const float* __restrict__ l3b,
    float* __restrict__ out)
{
    extern __shared__ unsigned char raw[];
    SmemM* S = (SmemM*)raw;
    const int t = threadIdx.x, lane = t & 31, wid = t >> 5;
    const int row0 = blockIdx.x * 32;

    for (int i = t; i < 32 * 128; i += 256) {
        int o = i >> 7, k4 = i & 127;
        S->w4[o * 129 + k4] = ((const float4*)l1w)[i];
    }
    for (int i = t; i < 32 * 32; i += 256)
        S->l2w[(i >> 5) * 33 + (i & 31)] = l2w[i];
    if (t < 32) { S->l3w[t] = l3w[t]; S->l1b[t] = l1b[t]; S->l2b[t] = l2b[t]; }
    if (t == 0) S->l3b = l3b[0];
    __syncthreads();

    const int r0 = wid * 4;
    const float4* wr = S->w4 + lane * 129;
    const float4* xa = ((const float4*)g_x) + (size_t)(row0 + r0) * 128;
    const float4* xb = xa + 128;
    const float4* xc = xb + 128;
    const float4* xd = xc + 128;
    float s0 = 0.f, s1 = 0.f, s2 = 0.f, s3 = 0.f;
#pragma unroll 8
    for (int k = 0; k < 128; k++) {
        float4 wv = wr[k];                            // 1 LDS.128 serves 4 rows
        float4 u = __ldg(xa + k), v = __ldg(xb + k);  // warp-uniform L2 loads,
        float4 p = __ldg(xc + k), q = __ldg(xd + k);  // independent -> batched
        s0 += ((wv.x * u.x + wv.y * u.y) + (wv.z * u.z + wv.w * u.w));
        s1 += ((wv.x * v.x + wv.y * v.y) + (wv.z * v.z + wv.w * v.w));
        s2 += ((wv.x * p.x + wv.y * p.y) + (wv.z * p.z + wv.w * p.w));
        s3 += ((wv.x * q.x + wv.y * q.y) + (wv.z * q.z + wv.w * q.w));
    }
    S->o1[(r0 + 0) * 33 + lane] = clamp01(s0 + S->l1b[lane]);
    S->o1[(r0 + 1) * 33 + lane] = clamp01(s1 + S->l1b[lane]);
    S->o1[(r0 + 2) * 33 + lane] = clamp01(s2 + S->l1b[lane]);
    S->o1[(r0 + 3) * 33 + lane] = clamp01(s3 + S->l1b[lane]);
    __syncwarp();

    float t0 = 0.f, t1 = 0.f, t2 = 0.f, t3 = 0.f;
#pragma unroll
    for (int k = 0; k < 32; k++) {
        float w2 = S->l2w[lane * 33 + k];             // (lane+k)%32: conflict-free
        t0 += w2 * S->o1[(r0 + 0) * 33 + k];
        t1 += w2 * S->o1[(r0 + 1) * 33 + k];
        t2 += w2 * S->o1[(r0 + 2) * 33 + k];
        t3 += w2 * S->o1[(r0 + 3) * 33 + k];
    }
    float v0 = clamp01(t0 + S->l2b[lane]) * S->l3w[lane];
    float v1 = clamp01(t1 + S->l2b[lane]) * S->l3w[lane];
    float v2 = clamp01(t2 + S->l2b[lane]) * S->l3w[lane];
    float v3 = clamp01(t3 + S->l2b[lane]) * S->l3w[lane];
#pragma unroll
    for (int off = 16; off; off >>= 1) {
        v0 += __shfl_xor_sync(FULL, v0, off);
        v1 += __shfl_xor_sync(FULL, v1, off);
        v2 += __shfl_xor_sync(FULL, v2, off);
        v3 += __shfl_xor_sync(FULL, v3, off);
    }
    if (lane == 0) {
        float b = S->l3b;
        out[row0 + r0 + 0] = 1.f / (1.f + expf(-(v0 + b) * 1.5f));  // 300/200
        out[row0 + r0 + 1] = 1.f / (1.f + expf(-(v1 + b) * 1.5f));
        out[row0 + r0 + 2] = 1.f / (1.f + expf(-(v2 + b) * 1.5f));
        out[row0 + r0 + 3] = 1.f / (1.f + expf(-(v3 + b) * 1.5f));
    }
}

extern "C" void kernel_launch(void* const* d_in, const int* in_sizes, int n_in,
                              void* d_out, int out_size) {
    const float* wf  = (const float*)d_in[0];
    const float* bf  = (const float*)d_in[1];
    const void*  side = d_in[2];
    const float* ftw = (const float*)d_in[3];
    const float* ftb = (const float*)d_in[4];
    const float* l1w = (const float*)d_in[5];
    const float* l1b = (const float*)d_in[6];
    const float* l2w = (const float*)d_in[7];
    const float* l2b = (const float*)d_in[8];
    const float* l3w = (const float*)d_in[9];
    const float* l3b = (const float*)d_in[10];
    float* out = (float*)d_out;

    cudaFuncSetAttribute(mlp_kernel, cudaFuncAttributeMaxDynamicSharedMemorySize,
                         (int)sizeof(SmemM));

    transpose_ft<<<dim3(N_IN / 32, H0 / 32), dim3(32, 8)>>>(
        ftw, (const unsigned int*)side);
    ft_kernel<<<NB * 2, 256>>>(wf, bf, side, ftb);
    mlp_kernel<<<NB / 32, 256, sizeof(SmemM)>>>(l1w, l1b, l2w, l2b, l3w, l3b, out);
}

// round 12
// speedup vs baseline: 1.0614x; 1.0481x over previous
#include <cuda_runtime.h>
#include <math.h>

#define N_IN 12288
#define H0 256
#define H1 32
#define H2 32
#define NB 8192
#define SEG_CAP 32        // per-warp-slice capacity (Binomial(1536,.0025): mean 3.8, z>14 safe)
#define FULL 0xffffffffu

// Transposed ft weights: column j = 256 contiguous floats (12.6 MB, L2-resident).
__device__ float g_ftT[N_IN * H0];
// MLP-ready inputs: [row][512], already side-swapped, +ftb, clamped (16 MB).
__device__ float g_x[NB * 2 * H0];
// 0 = 32-bit words (int32/fp32; !=0 covers both), 1 = packed bytes.
__device__ int g_side_mode;

__device__ __forceinline__ unsigned smem_u32(const void* p) {
    unsigned a;
    asm("{ .reg .u64 t; cvta.to.shared.u64 t, %1; cvt.u32.u64 %0, t; }"
        : "=r"(a) : "l"(p));
    return a;
}
__device__ __forceinline__ void cp16(unsigned dst, const void* src) {
    asm volatile("cp.async.cg.shared.global [%0], [%1], 16;"
                 :: "r"(dst), "l"(src) : "memory");
}

__global__ void transpose_ft(const float* __restrict__ ftw,
                             const unsigned int* __restrict__ side_words) {
    // Folded side-mode detection: block (0,0), warp 0 (saves a serial launch).
    if (blockIdx.x == 0 && blockIdx.y == 0 && threadIdx.y == 0) {
        int lane = threadIdx.x;
        bool bad = false;
#pragma unroll
        for (int i = 0; i < 8; i++) {
            unsigned int v = side_words[i * 32 + lane];   // 1 KB sample
            bad |= (v != 0u && v != 1u && v != 0x3f800000u);
        }
        unsigned m = __ballot_sync(FULL, bad);
        if (lane == 0) g_side_mode = (m != 0u) ? 1 : 0;
    }
    __shared__ float tile[32][33];
    int j0 = blockIdx.x * 32, h0 = blockIdx.y * 32;
    int tx = threadIdx.x, ty = threadIdx.y;
#pragma unroll
    for (int r = 0; r < 32; r += 8)
        tile[ty + r][tx] = ftw[(size_t)(h0 + ty + r) * N_IN + j0 + tx];
    __syncthreads();
#pragma unroll
    for (int r = 0; r < 32; r += 8)
        g_ftT[(size_t)(j0 + ty + r) * H0 + h0 + tx] = tile[tx][ty + r];
}

__device__ __forceinline__ float clamp01(float x) { return fminf(fmaxf(x, 0.f), 1.f); }
__device__ __forceinline__ void add4(float4& a, float4 u) {
    a.x += u.x; a.y += u.y; a.z += u.z; a.w += u.w;
}

// ============================================================================
// FT (fused scan+gather): one CTA per row-side. DRAM streaming (__ldcs,
// evict-first) overlaps with other CTAs' L2 gathers. Epilogue resolves
// side-swap, adds ftb, clamps -> g_x is MLP-ready.
// (Unchanged: profiled at the DRAM roofline, ~115us for 800MB.)
// ============================================================================
__global__ __launch_bounds__(256) void ft_kernel(
    const float* __restrict__ wf, const float* __restrict__ bf,
    const void* __restrict__ side, const float* __restrict__ ftb)
{
    __shared__ unsigned short lists[8][SEG_CAP];
    __shared__ int cnts[8];
    __shared__ float partial[8][H0];

    const int R = blockIdx.x;                       // row-side: row=R>>1, color=R&1
    const int row = R >> 1, color = R & 1;
    const float* base = color ? bf : wf;
    const uint4* rowp = (const uint4*)(base + (size_t)row * N_IN);
    const int t = threadIdx.x, lane = t & 31, wid = t >> 5;
    const unsigned lt = (1u << lane) - 1u;

    // ---- front-batched stream (12x LDG.128/thread), evict-first in L2 ----
    uint4 st[12];
#pragma unroll
    for (int i = 0; i < 12; i++) st[i] = __ldcs(rowp + i * 256 + t);

    // ---- ballot/popc compaction into per-warp smem segment ----
    int n = 0;
    unsigned short* seg = lists[wid];
#pragma unroll
    for (int i = 0; i < 12; i++) {
        uint4 v = st[i];
        bool f0 = v.x != 0u, f1 = v.y != 0u, f2 = v.z != 0u, f3 = v.w != 0u;
        unsigned b0 = __ballot_sync(FULL, f0);
        unsigned b1 = __ballot_sync(FULL, f1);
        unsigned b2 = __ballot_sync(FULL, f2);
        unsigned b3 = __ballot_sync(FULL, f3);
        if (b0 | b1 | b2 | b3) {                     // ~96% all-zero warp-wide
            int ib = (i * 256 + t) * 4;
            int c0 = __popc(b0), c01 = c0 + __popc(b1), c012 = c01 + __popc(b2);
            if (f0) { int q = n + __popc(b0 & lt);        if (q < SEG_CAP) seg[q] = (unsigned short)ib; }
            if (f1) { int q = n + c0 + __popc(b1 & lt);   if (q < SEG_CAP) seg[q] = (unsigned short)(ib + 1); }
            if (f2) { int q = n + c01 + __popc(b2 & lt);  if (q < SEG_CAP) seg[q] = (unsigned short)(ib + 2); }
            if (f3) { int q = n + c012 + __popc(b3 & lt); if (q < SEG_CAP) seg[q] = (unsigned short)(ib + 3); }
            n += c012 + __popc(b3);
        }
    }
    if (lane == 0) cnts[wid] = min(n, SEG_CAP);
    __syncthreads();

    // ---- gather: warp w takes global positions p ≡ w (mod 8) ----
    float4 a0 = make_float4(0, 0, 0, 0), a1 = a0;
    const float4* tab = (const float4*)g_ftT;
    {
        int gpos = 0;
#pragma unroll
        for (int s = 0; s < 8; s++) {
            int c = cnts[s];
            int p0 = gpos + ((wid - gpos) & 7);      // first p ≥ gpos with p%8==wid
            const unsigned short* sl = lists[s];
            for (int p = p0; p < gpos + c; p += 8) {
                int idx = sl[p - gpos];              // warp-uniform broadcast
                const float4* cp = tab + idx * 64 + lane * 2;
                float4 u0 = cp[0], u1 = cp[1];
                add4(a0, u0); add4(a1, u1);
            }
            gpos += c;
        }
    }
    ((float4*)partial[wid])[lane * 2]     = a0;
    ((float4*)partial[wid])[lane * 2 + 1] = a1;
    __syncthreads();

    // ---- fixed-order 8-way reduce + ftb + clamp + side-swap resolve ----
    float sum = partial[0][t];
#pragma unroll
    for (int w = 1; w < 8; w++) sum += partial[w][t];
    sum = clamp01(sum + ftb[t]);

    bool sd = g_side_mode ? (((const unsigned char*)side)[row] != 0)
                          : (((const unsigned int*)side)[row] != 0u);
    // reference: acc = side ? [w,b] : [b,w]; color 0 = white
    int half = (color == 0) ? (sd ? 0 : 1) : (sd ? 1 : 0);
    g_x[(size_t)row * 2 * H0 + half * H0 + t] = sum;
}

// ============================================================================
// MLP v4: g_x is DRAM-resident by the time this runs (ft's 800MB stream
// evicted it) -> stage x AND weights via cp.async (register-free, unbounded
// outstanding depth) so the 16MB fetch is BW-bound, not latency-bound.
// 32 rows/CTA, 4 rows/warp; compute from smem (conflict-free layouts).
// ============================================================================
struct SmemM {
    float4 w4[32 * 129];     // l1w, stride 129 -> conflict-free LDS.128
    float4 x4[32 * 128];     // 32 rows x 512 inputs
    float o1[32 * 33];
    float l2w[32 * 33];      // (lane+k)%32 conflict-free
    float l3w[32], l1b[32], l2b[32];
    float l3b;
};

__global__ __launch_bounds__(256) void mlp_kernel(
    const float* __restrict__ l1w, const float* __restrict__ l1b,
    const float* __restrict__ l2w, const float* __restrict__ l2b,
    const float* __restrict__ l3w, const float* __restrict__ l3b,
    float* __restrict__ out)
{
    extern __shared__ unsigned char raw[];
    SmemM* S = (SmemM*)raw;
    const int t = threadIdx.x, lane = t & 31, wid = t >> 5;
    const int row0 = blockIdx.x * 32;

    // ---- cp.async staging: 32 x 16B per thread, all in flight at once ----
    {
        const float4* wsrc = (const float4*)l1w;
        const float4* xsrc = ((const float4*)g_x) + (size_t)row0 * 128;
#pragma unroll
        for (int j = 0; j < 16; j++) {               // x tile: 4096 float4
            int i = j * 256 + t;
            cp16(smem_u32(&S->x4[i]), xsrc + i);
        }
#pragma unroll
        for (int j = 0; j < 16; j++) {               // l1w: strided dst, 16B each
            int i = j * 256 + t;
            int o = i >> 7, k4 = i & 127;
            cp16(smem_u32(&S->w4[o * 129 + k4]), wsrc + i);
        }
        asm volatile("cp.async.commit_group;" ::: "memory");
    }
    for (int i = t; i < 32 * 32; i += 256)
        S->l2w[(i >> 5) * 33 + (i & 31)] = l2w[i];
    if (t < 32) { S->l3w[t] = l3w[t]; S->l1b[t] = l1b[t]; S->l2b[t] = l2b[t]; }
    if (t == 0) S->l3b = l3b[0];
    asm volatile("cp.async.wait_group 0;" ::: "memory");
    __syncthreads();

    const int r0 = wid * 4;
    const float4* wr = S->w4 + lane * 129;
    const float4* xa = S->x4 + (r0 + 0) * 128;
    const float4* xb = S->x4 + (r0 + 1) * 128;
    const float4* xc = S->x4 + (r0 + 2) * 128;
    const float4* xd = S->x4 + (r0 + 3) * 128;
    float s0 = 0.f, s1 = 0.f, s2 = 0.f, s3 = 0.f;
#pragma unroll 4
    for (int k = 0; k < 128; k++) {
        float4 wv = wr[k];                            // 1 LDS.128 serves 4 rows
        float4 u = xa[k], v = xb[k], p = xc[k], q = xd[k];   // broadcast reads
        s0 += ((wv.x * u.x + wv.y * u.y) + (wv.z * u.z + wv.w * u.w));
        s1 += ((wv.x * v.x + wv.y * v.y) + (wv.z * v.z + wv.w * v.w));
        s2 += ((wv.x * p.x + wv.y * p.y) + (wv.z * p.z + wv.w * p.w));
        s3 += ((wv.x * q.x + wv.y * q.y) + (wv.z * q.z + wv.w * q.w));
    }
    S->o1[(r0 + 0) * 33 + lane] = clamp01(s0 + S->l1b[lane]);
    S->o1[(r0 + 1) * 33 + lane] = clamp01(s1 + S->l1b[lane]);
    S->o1[(r0 + 2) * 33 + lane] = clamp01(s2 + S->l1b[lane]);
    S->o1[(r0 + 3) * 33 + lane] = clamp01(s3 + S->l1b[lane]);
    __syncwarp();

    float t0 = 0.f, t1 = 0.f, t2 = 0.f, t3 = 0.f;
#pragma unroll
    for (int k = 0; k < 32; k++) {
        float w2 = S->l2w[lane * 33 + k];             // (lane+k)%32: conflict-free
        t0 += w2 * S->o1[(r0 + 0) * 33 + k];
        t1 += w2 * S->o1[(r0 + 1) * 33 + k];
        t2 += w2 * S->o1[(r0 + 2) * 33 + k];
        t3 += w2 * S->o1[(r0 + 3) * 33 + k];
    }
    float v0 = clamp01(t0 + S->l2b[lane]) * S->l3w[lane];
    float v1 = clamp01(t1 + S->l2b[lane]) * S->l3w[lane];
    float v2 = clamp01(t2 + S->l2b[lane]) * S->l3w[lane];
    float v3 = clamp01(t3 + S->l2b[lane]) * S->l3w[lane];
#pragma unroll
    for (int off = 16; off; off >>= 1) {
        v0 += __shfl_xor_sync(FULL, v0, off);
        v1 += __shfl_xor_sync(FULL, v1, off);
        v2 += __shfl_xor_sync(FULL, v2, off);
        v3 += __shfl_xor_sync(FULL, v3, off);
    }
    if (lane == 0) {
        float b = S->l3b;
        out[row0 + r0 + 0] = 1.f / (1.f + expf(-(v0 + b) * 1.5f));  // 300/200
        out[row0 + r0 + 1] = 1.f / (1.f + expf(-(v1 + b) * 1.5f));
        out[row0 + r0 + 2] = 1.f / (1.f + expf(-(v2 + b) * 1.5f));
        out[row0 + r0 + 3] = 1.f / (1.f + expf(-(v3 + b) * 1.5f));
    }
}

extern "C" void kernel_launch(void* const* d_in, const int* in_sizes, int n_in,
                              void* d_out, int out_size) {
    const float* wf  = (const float*)d_in[0];
    const float* bf  = (const float*)d_in[1];
    const void*  side = d_in[2];
    const float* ftw = (const float*)d_in[3];
    const float* ftb = (const float*)d_in[4];
    const float* l1w = (const float*)d_in[5];
    const float* l1b = (const float*)d_in[6];
    const float* l2w = (const float*)d_in[7];
    const float* l2b = (const float*)d_in[8];
    const float* l3w = (const float*)d_in[9];
    const float* l3b = (const float*)d_in[10];
    float* out = (float*)d_out;

    cudaFuncSetAttribute(mlp_kernel, cudaFuncAttributeMaxDynamicSharedMemorySize,
                         (int)sizeof(SmemM));

    transpose_ft<<<dim3(N_IN / 32, H0 / 32), dim3(32, 8)>>>(
        ftw, (const unsigned int*)side);
    ft_kernel<<<NB * 2, 256>>>(wf, bf, side, ftb);
    mlp_kernel<<<NB / 32, 256, sizeof(SmemM)>>>(l1w, l1b, l2w, l2b, l3w, l3b, out);
}